// round 3
// baseline (speedup 1.0000x reference)
#include <cuda_runtime.h>

// CombPool2d: out = (w_avg^2)*avg_pool2x2(x) + (w_max^2)*max_pool2x2(x)
// x: (16,192,224,224) fp32, out: (16,192,112,112) fp32. Pure HBM stream.
// 8 output pixels per thread: 8x float4 loads front-batched (MLP=8),
// 2x float4 stores, streaming cache hints (each byte touched once).

#define B   16
#define C   192
#define HI  224
#define WI  224
#define HO  112
#define WO  112
#define WE  (WO / 8)   // output octets per row = 14

__global__ __launch_bounds__(256)
void comb_pool2d_kernel(const float* __restrict__ x,
                        const float* __restrict__ w_avg,
                        const float* __restrict__ w_max,
                        float* __restrict__ out)
{
    const int total = B * C * HO * WE;            // 4,816,896
    int tid = blockIdx.x * blockDim.x + threadIdx.x;
    if (tid >= total) return;

    int we = tid % WE;          // which octet of output columns
    int t  = tid / WE;
    int h  = t % HO;            // output row
    int bc = t / HO;            // fused batch*channel index
    int c  = bc % C;

    // Input base: rows 2h, 2h+1; cols 16*we .. 16*we+15 (2x16 patch)
    const float4* xin = reinterpret_cast<const float4*>(
        x + (size_t)bc * (HI * WI) + (size_t)(2 * h) * WI + 16 * we);

    // Front-batch all eight 16B loads (MLP=8, coalesced, evict-first)
    float4 r0a = __ldcs(xin);
    float4 r0b = __ldcs(xin + 1);
    float4 r0c = __ldcs(xin + 2);
    float4 r0d = __ldcs(xin + 3);
    float4 r1a = __ldcs(xin + WI / 4);
    float4 r1b = __ldcs(xin + WI / 4 + 1);
    float4 r1c = __ldcs(xin + WI / 4 + 2);
    float4 r1d = __ldcs(xin + WI / 4 + 3);

    float wa = __ldg(w_avg + c);
    float wm = __ldg(w_max + c);
    float ca = wa * wa * 0.25f;   // folds the /4 of avg-pool
    float cm = wm * wm;

    float4 o0, o1;

    o0.x = fmaf(ca, (r0a.x + r0a.y) + (r1a.x + r1a.y),
                cm * fmaxf(fmaxf(r0a.x, r0a.y), fmaxf(r1a.x, r1a.y)));
    o0.y = fmaf(ca, (r0a.z + r0a.w) + (r1a.z + r1a.w),
                cm * fmaxf(fmaxf(r0a.z, r0a.w), fmaxf(r1a.z, r1a.w)));
    o0.z = fmaf(ca, (r0b.x + r0b.y) + (r1b.x + r1b.y),
                cm * fmaxf(fmaxf(r0b.x, r0b.y), fmaxf(r1b.x, r1b.y)));
    o0.w = fmaf(ca, (r0b.z + r0b.w) + (r1b.z + r1b.w),
                cm * fmaxf(fmaxf(r0b.z, r0b.w), fmaxf(r1b.z, r1b.w)));

    o1.x = fmaf(ca, (r0c.x + r0c.y) + (r1c.x + r1c.y),
                cm * fmaxf(fmaxf(r0c.x, r0c.y), fmaxf(r1c.x, r1c.y)));
    o1.y = fmaf(ca, (r0c.z + r0c.w) + (r1c.z + r1c.w),
                cm * fmaxf(fmaxf(r0c.z, r0c.w), fmaxf(r1c.z, r1c.w)));
    o1.z = fmaf(ca, (r0d.x + r0d.y) + (r1d.x + r1d.y),
                cm * fmaxf(fmaxf(r0d.x, r0d.y), fmaxf(r1d.x, r1d.y)));
    o1.w = fmaf(ca, (r0d.z + r0d.w) + (r1d.z + r1d.w),
                cm * fmaxf(fmaxf(r0d.z, r0d.w), fmaxf(r1d.z, r1d.w)));

    float4* outp = reinterpret_cast<float4*>(
        out + (size_t)bc * (HO * WO) + (size_t)h * WO + 8 * we);
    __stcs(outp,     o0);
    __stcs(outp + 1, o1);
}

extern "C" void kernel_launch(void* const* d_in, const int* in_sizes, int n_in,
                              void* d_out, int out_size)
{
    const float* x     = (const float*)d_in[0];
    const float* w_avg = (const float*)d_in[1];
    const float* w_max = (const float*)d_in[2];
    float* out = (float*)d_out;

    const int total   = B * C * HO * WE;           // 4,816,896
    const int threads = 256;
    const int blocks  = (total + threads - 1) / threads;  // 18,816 exactly

    comb_pool2d_kernel<<<blocks, threads>>>(x, w_avg, w_max, out);
}

// round 4
// speedup vs baseline: 1.1015x; 1.1015x over previous
#include <cuda_runtime.h>

// CombPool2d: out = (w_avg^2)*avg_pool2x2(x) + (w_max^2)*max_pool2x2(x)
// x: (16,192,224,224) fp32, out: (16,192,112,112) fp32. Pure HBM stream.
// Thread = 2x2 output block: 4x float4 loads from 4 consecutive input rows
// (every LDG.128 lane-contiguous, MLP_p1=4), 2x float2 stores (lane-contiguous).

#define B   16
#define C   192
#define HI  224
#define WI  224
#define HO  112
#define WO  112
#define H2  (HO / 2)   // output row-pairs = 56
#define WP  (WO / 2)   // output col-pairs = 56

__global__ __launch_bounds__(256)
void comb_pool2d_kernel(const float* __restrict__ x,
                        const float* __restrict__ w_avg,
                        const float* __restrict__ w_max,
                        float* __restrict__ out)
{
    const int total = B * C * H2 * WP;            // 9,633,792
    int tid = blockIdx.x * blockDim.x + threadIdx.x;
    if (tid >= total) return;

    int wp = tid % WP;          // output col-pair (2 output cols)
    int t  = tid / WP;
    int h2 = t % H2;            // output row-pair (2 output rows)
    int bc = t / H2;            // fused batch*channel
    int c  = bc % C;

    // Input: rows 4*h2 .. 4*h2+3, cols 4*wp .. 4*wp+3 (4x4 patch, 16B/row)
    const float* xin = x + (size_t)bc * (HI * WI) + (size_t)(4 * h2) * WI + 4 * wp;

    // Four lane-contiguous 16B loads, front-batched (MLP=4, evict-first)
    float4 r0 = __ldcs(reinterpret_cast<const float4*>(xin));
    float4 r1 = __ldcs(reinterpret_cast<const float4*>(xin + WI));
    float4 r2 = __ldcs(reinterpret_cast<const float4*>(xin + 2 * WI));
    float4 r3 = __ldcs(reinterpret_cast<const float4*>(xin + 3 * WI));

    float wa = __ldg(w_avg + c);
    float wm = __ldg(w_max + c);
    float ca = wa * wa * 0.25f;   // folds the /4 of avg-pool
    float cm = wm * wm;

    float2 o0, o1;
    // rows (r0, r1) -> output row 2*h2
    o0.x = fmaf(ca, (r0.x + r0.y) + (r1.x + r1.y),
                cm * fmaxf(fmaxf(r0.x, r0.y), fmaxf(r1.x, r1.y)));
    o0.y = fmaf(ca, (r0.z + r0.w) + (r1.z + r1.w),
                cm * fmaxf(fmaxf(r0.z, r0.w), fmaxf(r1.z, r1.w)));
    // rows (r2, r3) -> output row 2*h2+1
    o1.x = fmaf(ca, (r2.x + r2.y) + (r3.x + r3.y),
                cm * fmaxf(fmaxf(r2.x, r2.y), fmaxf(r3.x, r3.y)));
    o1.y = fmaf(ca, (r2.z + r2.w) + (r3.z + r3.w),
                cm * fmaxf(fmaxf(r2.z, r2.w), fmaxf(r3.z, r3.w)));

    float* outp = out + (size_t)bc * (HO * WO) + (size_t)(2 * h2) * WO + 2 * wp;
    __stcs(reinterpret_cast<float2*>(outp),      o0);
    __stcs(reinterpret_cast<float2*>(outp + WO), o1);
}

extern "C" void kernel_launch(void* const* d_in, const int* in_sizes, int n_in,
                              void* d_out, int out_size)
{
    const float* x     = (const float*)d_in[0];
    const float* w_avg = (const float*)d_in[1];
    const float* w_max = (const float*)d_in[2];
    float* out = (float*)d_out;

    const int total   = B * C * H2 * WP;           // 9,633,792
    const int threads = 256;
    const int blocks  = (total + threads - 1) / threads;  // 37,632 exactly

    comb_pool2d_kernel<<<blocks, threads>>>(x, w_avg, w_max, out);
}

// round 5
// speedup vs baseline: 1.1077x; 1.0056x over previous
#include <cuda_runtime.h>

// CombPool2d: out = (w_avg^2)*avg_pool2x2(x) + (w_max^2)*max_pool2x2(x)
// x: (16,192,224,224) fp32, out: (16,192,112,112) fp32. Pure HBM stream.
// Thread = 2x2 output block: 4x lane-contiguous float4 loads (MLP_p1=4),
// 2x float2 stores. 2D grid: blockIdx.y = fused batch*channel (no big divs),
// exact fit (3136 threads per image plane = 7 blocks x 448), no bounds guard.

#define B   16
#define C   192
#define HI  224
#define WI  224
#define HO  112
#define WO  112
#define H2  (HO / 2)   // output row-pairs = 56
#define WP  (WO / 2)   // output col-pairs = 56
#define TPB 448        // 14 warps; 7 * 448 = 3136 = H2 * WP exactly

__global__ __launch_bounds__(TPB)
void comb_pool2d_kernel(const float* __restrict__ x,
                        const float* __restrict__ w_avg,
                        const float* __restrict__ w_max,
                        float* __restrict__ out)
{
    // blockIdx.y = bc (0..3071), blockIdx.x*TPB + tid covers the 56x56 plane
    int bc  = blockIdx.y;
    int pix = blockIdx.x * TPB + threadIdx.x;   // 0..3135, exact
    int wp  = pix % WP;
    int h2  = pix / WP;
    int c   = bc % C;

    // Input: rows 4*h2 .. 4*h2+3, cols 4*wp .. 4*wp+3 (4x4 patch, 16B/row)
    const float* xin = x + (size_t)bc * (HI * WI) + (size_t)(4 * h2) * WI + 4 * wp;

    // Four lane-contiguous 16B loads, front-batched (MLP=4, evict-first)
    float4 r0 = __ldcs(reinterpret_cast<const float4*>(xin));
    float4 r1 = __ldcs(reinterpret_cast<const float4*>(xin + WI));
    float4 r2 = __ldcs(reinterpret_cast<const float4*>(xin + 2 * WI));
    float4 r3 = __ldcs(reinterpret_cast<const float4*>(xin + 3 * WI));

    float wa = __ldg(w_avg + c);
    float wm = __ldg(w_max + c);
    float ca = wa * wa * 0.25f;   // folds the /4 of avg-pool
    float cm = wm * wm;

    float2 o0, o1;
    // rows (r0, r1) -> output row 2*h2
    o0.x = fmaf(ca, (r0.x + r0.y) + (r1.x + r1.y),
                cm * fmaxf(fmaxf(r0.x, r0.y), fmaxf(r1.x, r1.y)));
    o0.y = fmaf(ca, (r0.z + r0.w) + (r1.z + r1.w),
                cm * fmaxf(fmaxf(r0.z, r0.w), fmaxf(r1.z, r1.w)));
    // rows (r2, r3) -> output row 2*h2+1
    o1.x = fmaf(ca, (r2.x + r2.y) + (r3.x + r3.y),
                cm * fmaxf(fmaxf(r2.x, r2.y), fmaxf(r3.x, r3.y)));
    o1.y = fmaf(ca, (r2.z + r2.w) + (r3.z + r3.w),
                cm * fmaxf(fmaxf(r2.z, r2.w), fmaxf(r3.z, r3.w)));

    float* outp = out + (size_t)bc * (HO * WO) + (size_t)(2 * h2) * WO + 2 * wp;
    __stcs(reinterpret_cast<float2*>(outp),      o0);
    __stcs(reinterpret_cast<float2*>(outp + WO), o1);
}

extern "C" void kernel_launch(void* const* d_in, const int* in_sizes, int n_in,
                              void* d_out, int out_size)
{
    const float* x     = (const float*)d_in[0];
    const float* w_avg = (const float*)d_in[1];
    const float* w_max = (const float*)d_in[2];
    float* out = (float*)d_out;

    dim3 grid((H2 * WP) / TPB, B * C);   // (7, 3072), exact fit
    comb_pool2d_kernel<<<grid, TPB>>>(x, w_avg, w_max, out);
}